// round 1
// baseline (speedup 1.0000x reference)
#include <cuda_runtime.h>

// Problem shape (fixed by the dataset):
//   x  [4,2048,2048] f32  -> M = 8192 tokens, D = 2048
//   w1 [8192,2048]   f32  -> H = 8192
//   w2 [2048,8192]   f32
//   out[4,2048,2048] f32
#define TOKS 8192
#define DDIM 2048
#define HDIM 8192
#define EPSV 1e-5f

typedef signed char s8;

// ---- scratch (static device globals: allocation-free) ----
__device__ s8    g_xq [(size_t)TOKS * DDIM];     // 16.7 MB
__device__ s8    g_w1q[(size_t)HDIM * DDIM];     // 16.7 MB
__device__ s8    g_w2q[(size_t)DDIM * HDIM];     // 16.7 MB
__device__ s8    g_hq [(size_t)TOKS * HDIM];     // 67 MB
__device__ float g_h2 [(size_t)TOKS * HDIM];     // 268 MB
__device__ float g_xscale[TOKS];
__device__ float g_hscale[TOKS];
__device__ float g_partial[4096];
__device__ float g_wmean[2];

// ---------------------------------------------------------------------------
// mean(|w|) over 16,777,216 elements: deterministic two-pass tree reduction.
// ---------------------------------------------------------------------------
__global__ void absmean_partial(const float* __restrict__ w) {
    // 4096 blocks x 256 threads, 4096 elements (1024 float4) per block
    const float4* w4 = (const float4*)(w + (size_t)blockIdx.x * 4096);
    float s = 0.f;
#pragma unroll
    for (int i = 0; i < 4; i++) {
        float4 v = w4[threadIdx.x + i * 256];
        s += fabsf(v.x) + fabsf(v.y) + fabsf(v.z) + fabsf(v.w);
    }
    __shared__ float red[256];
    red[threadIdx.x] = s;
    __syncthreads();
    for (int o = 128; o > 0; o >>= 1) {
        if (threadIdx.x < o) red[threadIdx.x] += red[threadIdx.x + o];
        __syncthreads();
    }
    if (threadIdx.x == 0) g_partial[blockIdx.x] = red[0];
}

__global__ void absmean_final(int idx) {
    __shared__ float red[1024];
    float s = g_partial[threadIdx.x] + g_partial[threadIdx.x + 1024] +
              g_partial[threadIdx.x + 2048] + g_partial[threadIdx.x + 3072];
    red[threadIdx.x] = s;
    __syncthreads();
    for (int o = 512; o > 0; o >>= 1) {
        if (threadIdx.x < o) red[threadIdx.x] += red[threadIdx.x + o];
        __syncthreads();
    }
    if (threadIdx.x == 0) {
        float mean = red[0] / 16777216.f;
        g_wmean[idx] = fmaxf(mean, EPSV);   // clip(mean,eps)
    }
}

// ---------------------------------------------------------------------------
// Ternary weight quantization: wq = clip(rint(w / mean), -1, 1)
// ---------------------------------------------------------------------------
__global__ void quantize_w(const float* __restrict__ w, int idx) {
    s8* wq = idx ? g_w2q : g_w1q;
    float inv = 1.f / g_wmean[idx];
    const float4* w4 = (const float4*)w;
    char4* q4 = (char4*)wq;
    const long n4 = (long)HDIM * DDIM / 4;
    long stride = (long)gridDim.x * blockDim.x;
    for (long k = (long)blockIdx.x * blockDim.x + threadIdx.x; k < n4; k += stride) {
        float4 v = w4[k];
        char4 o;
        o.x = (s8)(int)fmaxf(-1.f, fminf(1.f, rintf(v.x * inv)));
        o.y = (s8)(int)fmaxf(-1.f, fminf(1.f, rintf(v.y * inv)));
        o.z = (s8)(int)fmaxf(-1.f, fminf(1.f, rintf(v.z * inv)));
        o.w = (s8)(int)fmaxf(-1.f, fminf(1.f, rintf(v.w * inv)));
        q4[k] = o;
    }
}

// ---------------------------------------------------------------------------
// Per-token int8 absmax quantization. which==0: x (DDIM) -> g_xq/g_xscale
//                                     which==1: g_h2 (HDIM) -> g_hq/g_hscale
// ---------------------------------------------------------------------------
__global__ void quantize_rows(const float* __restrict__ Xin, int ncol, int which) {
    int row = blockIdx.x;
    const float* X  = (which == 0) ? Xin : (g_h2 + (size_t)row * ncol);
    if (which == 0) X = Xin + (size_t)row * ncol;
    s8*    Xq = (which == 0) ? (g_xq + (size_t)row * ncol) : (g_hq + (size_t)row * ncol);
    float* sc = (which == 0) ? g_xscale : g_hscale;

    const float4* x4 = (const float4*)X;
    int n4 = ncol >> 2;
    float mx = 0.f;
    for (int i = threadIdx.x; i < n4; i += blockDim.x) {
        float4 v = x4[i];
        mx = fmaxf(mx, fmaxf(fmaxf(fabsf(v.x), fabsf(v.y)),
                             fmaxf(fabsf(v.z), fabsf(v.w))));
    }
    __shared__ float red[256];
    red[threadIdx.x] = mx;
    __syncthreads();
    for (int o = 128; o > 0; o >>= 1) {
        if (threadIdx.x < o) red[threadIdx.x] = fmaxf(red[threadIdx.x], red[threadIdx.x + o]);
        __syncthreads();
    }
    float scale = 127.f / fmaxf(red[0], EPSV);
    if (threadIdx.x == 0) sc[row] = scale;

    char4* q4 = (char4*)Xq;
    for (int i = threadIdx.x; i < n4; i += blockDim.x) {
        float4 v = x4[i];
        char4 o;
        o.x = (s8)(int)fminf(127.f, fmaxf(-128.f, rintf(v.x * scale)));
        o.y = (s8)(int)fminf(127.f, fmaxf(-128.f, rintf(v.y * scale)));
        o.z = (s8)(int)fminf(127.f, fmaxf(-128.f, rintf(v.z * scale)));
        o.w = (s8)(int)fminf(127.f, fmaxf(-128.f, rintf(v.w * scale)));
        q4[i] = o;
    }
}

// ---------------------------------------------------------------------------
// Tiled int8 GEMM (dp4a): C[m,n] = sum_k A[m,k]*B[n,k]   (both K-contiguous)
// BM=BN=128, BK=32 bytes. 256 threads, 8x8 micro-tile per thread.
// mode 0: A=g_xq  (K=DDIM), B=g_w1q, epi: v=acc*mean0/xscale; g_h2=relu(v)^2
// mode 1: A=g_hq  (K=HDIM), B=g_w2q, epi: out=acc*mean1/hscale
// ---------------------------------------------------------------------------
__global__ __launch_bounds__(256, 1) void gemm_s8(int mode, float* __restrict__ outParam) {
    const int Kx = (mode == 0) ? DDIM : HDIM;
    const int Nx = (mode == 0) ? HDIM : DDIM;
    const s8* __restrict__ A = (mode == 0) ? g_xq : g_hq;
    const s8* __restrict__ B = (mode == 0) ? g_w1q : g_w2q;
    const float* __restrict__ rowScale = (mode == 0) ? g_xscale : g_hscale;
    float* __restrict__ outp = (mode == 0) ? g_h2 : outParam;
    const float wmean = g_wmean[mode];

    __shared__ int As[8][128];   // [kk][m]  (kk = packed-int32 index inside 32B k-tile)
    __shared__ int Bs[8][128];   // [kk][n]

    const int tid = threadIdx.x;
    const int ty = tid >> 4;      // 0..15 (row group)
    const int tx = tid & 15;      // 0..15 (col group)
    const int m0 = blockIdx.y * 128;
    const int n0 = blockIdx.x * 128;

    // global tile loaders: thread t loads one int4 (16B) of A and of B per k-tile
    const int lrow = tid >> 1;           // 0..127
    const int lseg = tid & 1;            // which 16B half of the 32B row chunk
    const int4* aPtr = (const int4*)(A + (size_t)(m0 + lrow) * Kx) + lseg;
    const int4* bPtr = (const int4*)(B + (size_t)(n0 + lrow) * Kx) + lseg;
    const int kkBase = lseg * 4;

    int acc[8][8];
#pragma unroll
    for (int i = 0; i < 8; i++)
#pragma unroll
        for (int j = 0; j < 8; j++) acc[i][j] = 0;

    const int ktiles = Kx >> 5;   // K / 32
    for (int tt = 0; tt < ktiles; tt++) {
        int4 av = aPtr[tt * 2];
        int4 bv = bPtr[tt * 2];
        __syncthreads();          // previous compute done before overwrite
        As[kkBase + 0][lrow] = av.x;
        As[kkBase + 1][lrow] = av.y;
        As[kkBase + 2][lrow] = av.z;
        As[kkBase + 3][lrow] = av.w;
        Bs[kkBase + 0][lrow] = bv.x;
        Bs[kkBase + 1][lrow] = bv.y;
        Bs[kkBase + 2][lrow] = bv.z;
        Bs[kkBase + 3][lrow] = bv.w;
        __syncthreads();

#pragma unroll
        for (int kk = 0; kk < 8; kk++) {
            int a[8], b[8];
#pragma unroll
            for (int i = 0; i < 8; i++) a[i] = As[kk][ty + i * 16];
#pragma unroll
            for (int j = 0; j < 8; j++) b[j] = Bs[kk][tx + j * 16];
#pragma unroll
            for (int i = 0; i < 8; i++)
#pragma unroll
                for (int j = 0; j < 8; j++)
                    acc[i][j] = __dp4a(a[i], b[j], acc[i][j]);
        }
    }

    // epilogue
#pragma unroll
    for (int i = 0; i < 8; i++) {
        const int m = m0 + ty + i * 16;
        const float fac = wmean / rowScale[m];   // == mean|w| / (127/maxabs)
        float* orow = outp + (size_t)m * Nx + n0 + tx;
        if (mode == 0) {
#pragma unroll
            for (int j = 0; j < 8; j++) {
                float v = (float)acc[i][j] * fac;
                float r = fmaxf(v, 0.f);
                orow[j * 16] = r * r;            // squared ReLU
            }
        } else {
#pragma unroll
            for (int j = 0; j < 8; j++) {
                orow[j * 16] = (float)acc[i][j] * fac;
            }
        }
    }
}

// ---------------------------------------------------------------------------
extern "C" void kernel_launch(void* const* d_in, const int* in_sizes, int n_in,
                              void* d_out, int out_size) {
    const float* x  = (const float*)d_in[0];
    const float* w1 = (const float*)d_in[1];
    const float* w2 = (const float*)d_in[2];
    float* out = (float*)d_out;

    // weight scales (mean |w|), deterministic tree reductions
    absmean_partial<<<4096, 256>>>(w1);
    absmean_final<<<1, 1024>>>(0);
    absmean_partial<<<4096, 256>>>(w2);
    absmean_final<<<1, 1024>>>(1);

    // ternary weights
    quantize_w<<<4096, 256>>>(w1, 0);
    quantize_w<<<4096, 256>>>(w2, 1);

    // per-token int8 activations
    quantize_rows<<<TOKS, 256>>>(x, DDIM, 0);

    // h2 = relu(x_q @ w1_q^T)^2
    gemm_s8<<<dim3(HDIM / 128, TOKS / 128), 256>>>(0, nullptr);

    // re-quantize h2 per token
    quantize_rows<<<TOKS, 256>>>(nullptr, HDIM, 1);

    // out = h_q @ w2_q^T
    gemm_s8<<<dim3(DDIM / 128, TOKS / 128), 256>>>(1, out);
}

// round 3
// speedup vs baseline: 1.1802x; 1.1802x over previous
#include <cuda_runtime.h>
#include <cstdint>

// Shapes (fixed): x[4,2048,2048] -> M=8192 tokens, D=2048, H=8192
#define TOKS 8192
#define DDIM 2048
#define HDIM 8192
#define EPSV 1e-5f

typedef signed char s8;

// ---- scratch (static device globals: allocation-free) ----
__device__ s8    g_xq [(size_t)TOKS * DDIM];     // 16.7 MB
__device__ s8    g_w1q[(size_t)HDIM * DDIM];     // 16.7 MB
__device__ s8    g_w2q[(size_t)DDIM * HDIM];     // 16.7 MB
__device__ s8    g_hq [(size_t)TOKS * HDIM];     // 67 MB
__device__ float g_h2 [(size_t)TOKS * HDIM];     // 268 MB
__device__ float g_xscale[TOKS];
__device__ float g_hscale[TOKS];
__device__ float g_partial[4096];
__device__ float g_wmean[2];

// ============================ PTX helpers (all portable, non-'a') ============
__device__ __forceinline__ uint32_t smem_u32(const void* p) {
    uint32_t a;
    asm("{ .reg .u64 t; cvta.to.shared.u64 t, %1; cvt.u32.u64 %0, t; }" : "=r"(a) : "l"(p));
    return a;
}
__device__ __forceinline__ void cp16(uint32_t dst, const void* src) {
    asm volatile("cp.async.cg.shared.global [%0], [%1], 16;" :: "r"(dst), "l"(src));
}
__device__ __forceinline__ void cp_commit() {
    asm volatile("cp.async.commit_group;" ::: "memory");
}
template <int N> __device__ __forceinline__ void cp_wait() {
    asm volatile("cp.async.wait_group %0;" :: "n"(N) : "memory");
}
#define LDSM4(r, addr)                                                          \
    asm volatile("ldmatrix.sync.aligned.m8n8.x4.shared.b16 {%0,%1,%2,%3}, [%4];" \
        : "=r"((r)[0]), "=r"((r)[1]), "=r"((r)[2]), "=r"((r)[3]) : "r"(addr))
#define MMA_S8(d, a, b0, b1)                                                    \
    asm volatile("mma.sync.aligned.m16n8k32.row.col.s32.s8.s8.s32 "             \
        "{%0,%1,%2,%3},{%4,%5,%6,%7},{%8,%9},{%0,%1,%2,%3};"                    \
        : "+r"((d)[0]), "+r"((d)[1]), "+r"((d)[2]), "+r"((d)[3])                \
        : "r"((a)[0]), "r"((a)[1]), "r"((a)[2]), "r"((a)[3]), "r"(b0), "r"(b1))

// ============================ reductions / quant ============================
__global__ void absmean_partial(const float* __restrict__ w) {
    const float4* w4 = (const float4*)(w + (size_t)blockIdx.x * 4096);
    float s = 0.f;
#pragma unroll
    for (int i = 0; i < 4; i++) {
        float4 v = w4[threadIdx.x + i * 256];
        s += fabsf(v.x) + fabsf(v.y) + fabsf(v.z) + fabsf(v.w);
    }
    __shared__ float red[256];
    red[threadIdx.x] = s;
    __syncthreads();
    for (int o = 128; o > 0; o >>= 1) {
        if (threadIdx.x < o) red[threadIdx.x] += red[threadIdx.x + o];
        __syncthreads();
    }
    if (threadIdx.x == 0) g_partial[blockIdx.x] = red[0];
}

__global__ void absmean_final(int idx) {
    __shared__ float red[1024];
    float s = g_partial[threadIdx.x] + g_partial[threadIdx.x + 1024] +
              g_partial[threadIdx.x + 2048] + g_partial[threadIdx.x + 3072];
    red[threadIdx.x] = s;
    __syncthreads();
    for (int o = 512; o > 0; o >>= 1) {
        if (threadIdx.x < o) red[threadIdx.x] += red[threadIdx.x + o];
        __syncthreads();
    }
    if (threadIdx.x == 0) g_wmean[idx] = fmaxf(red[0] / 16777216.f, EPSV);
}

__global__ void quantize_w(const float* __restrict__ w, int idx) {
    s8* wq = idx ? g_w2q : g_w1q;
    float inv = 1.f / g_wmean[idx];
    const float4* w4 = (const float4*)w;
    char4* q4 = (char4*)wq;
    const long n4 = (long)HDIM * DDIM / 4;
    long stride = (long)gridDim.x * blockDim.x;
    for (long k = (long)blockIdx.x * blockDim.x + threadIdx.x; k < n4; k += stride) {
        float4 v = w4[k];
        char4 o;
        o.x = (s8)(int)fmaxf(-1.f, fminf(1.f, rintf(v.x * inv)));
        o.y = (s8)(int)fmaxf(-1.f, fminf(1.f, rintf(v.y * inv)));
        o.z = (s8)(int)fmaxf(-1.f, fminf(1.f, rintf(v.z * inv)));
        o.w = (s8)(int)fmaxf(-1.f, fminf(1.f, rintf(v.w * inv)));
        q4[k] = o;
    }
}

__global__ void quantize_rows(const float* __restrict__ Xin, int ncol, int which) {
    int row = blockIdx.x;
    const float* X = (which == 0) ? (Xin + (size_t)row * ncol)
                                  : (g_h2 + (size_t)row * ncol);
    s8*    Xq = (which == 0) ? (g_xq + (size_t)row * ncol) : (g_hq + (size_t)row * ncol);
    float* sc = (which == 0) ? g_xscale : g_hscale;

    const float4* x4 = (const float4*)X;
    int n4 = ncol >> 2;
    float mx = 0.f;
    for (int i = threadIdx.x; i < n4; i += blockDim.x) {
        float4 v = x4[i];
        mx = fmaxf(mx, fmaxf(fmaxf(fabsf(v.x), fabsf(v.y)),
                             fmaxf(fabsf(v.z), fabsf(v.w))));
    }
    __shared__ float red[256];
    red[threadIdx.x] = mx;
    __syncthreads();
    for (int o = 128; o > 0; o >>= 1) {
        if (threadIdx.x < o) red[threadIdx.x] = fmaxf(red[threadIdx.x], red[threadIdx.x + o]);
        __syncthreads();
    }
    float scale = 127.f / fmaxf(red[0], EPSV);
    if (threadIdx.x == 0) sc[row] = scale;

    char4* q4 = (char4*)Xq;
    for (int i = threadIdx.x; i < n4; i += blockDim.x) {
        float4 v = x4[i];
        char4 o;
        o.x = (s8)(int)fminf(127.f, fmaxf(-128.f, rintf(v.x * scale)));
        o.y = (s8)(int)fminf(127.f, fmaxf(-128.f, rintf(v.y * scale)));
        o.z = (s8)(int)fminf(127.f, fmaxf(-128.f, rintf(v.z * scale)));
        o.w = (s8)(int)fminf(127.f, fmaxf(-128.f, rintf(v.w * scale)));
        q4[i] = o;
    }
}

// ============================ IMMA GEMM (mma.sync m16n8k32 s8) ==============
// C[m,n] = sum_k A[m,k]*B[n,k], both operands K-contiguous s8.
// CTA tile 128x128, BK=64 bytes/stage, 4-stage cp.async pipeline.
// 8 warps (4 m x 2 n), warp tile 32x64: 2 m16-tiles x 8 n8-tiles.
// Swizzle: row of 64B = 4 chunks of 16B; phys_chunk = chunk ^ ((row>>1)&3)
//   -> conflict-free ldmatrix (8 consecutive rows hit 8 distinct bank groups).
#define STAGES 4
#define STAGE_BYTES 16384        // A 128x64 (8KB) + B 128x64 (8KB)
#define GEMM_SMEM (STAGES * STAGE_BYTES)

__global__ __launch_bounds__(256, 1) void gemm_imma(int mode, float* __restrict__ outParam) {
    const int Kx = mode ? HDIM : DDIM;
    const int Nx = mode ? DDIM : HDIM;
    const s8* __restrict__ A = mode ? g_hq : g_xq;
    const s8* __restrict__ B = mode ? g_w2q : g_w1q;
    const float* __restrict__ rowScale = mode ? g_hscale : g_xscale;
    float* __restrict__ outp = mode ? outParam : g_h2;
    const float wmean = g_wmean[mode];

    extern __shared__ char smem[];
    const uint32_t sbase = smem_u32(smem);

    const int tid = threadIdx.x;
    const int wid = tid >> 5;
    const int lane = tid & 31;
    const int warp_m = wid >> 1;      // 0..3
    const int warp_n = wid & 1;       // 0..1
    const int q  = lane >> 3;         // ldmatrix matrix id
    const int r8 = lane & 7;          // row within 8x8 matrix
    const int m0 = blockIdx.y * 128;
    const int n0 = blockIdx.x * 128;

    // ---- ldmatrix smem offsets (within a stage) ----
    // A tile at +0, B tile at +8192. Row stride 64B.
    uint32_t offA[2][2], offB[4][2];
#pragma unroll
    for (int mt = 0; mt < 2; mt++) {
        int row = warp_m * 32 + mt * 16 + (q & 1) * 8 + r8;
        int key = (row >> 1) & 3;
#pragma unroll
        for (int ks = 0; ks < 2; ks++) {
            int c = ks * 2 + (q >> 1);
            offA[mt][ks] = (uint32_t)(row * 64 + ((c ^ key) * 16));
        }
    }
#pragma unroll
    for (int g = 0; g < 4; g++) {
        int row = warp_n * 64 + g * 16 + (q >> 1) * 8 + r8;
        int key = (row >> 1) & 3;
#pragma unroll
        for (int ks = 0; ks < 2; ks++) {
            int c = ks * 2 + (q & 1);
            offB[g][ks] = (uint32_t)(8192 + row * 64 + ((c ^ key) * 16));
        }
    }

    // ---- global loader geometry: 2 x 16B per operand per thread per stage ----
    int lrow[2], lchunk[2];
    uint32_t soffA[2], soffB[2];
    const s8* gA[2];
    const s8* gB[2];
#pragma unroll
    for (int h = 0; h < 2; h++) {
        int linear = tid + 256 * h;       // 0..511
        lrow[h] = linear >> 2;            // 0..127
        lchunk[h] = linear & 3;
        int pc = lchunk[h] ^ ((lrow[h] >> 1) & 3);
        soffA[h] = (uint32_t)(lrow[h] * 64 + pc * 16);
        soffB[h] = (uint32_t)(8192 + lrow[h] * 64 + pc * 16);
        gA[h] = A + (size_t)(m0 + lrow[h]) * Kx + lchunk[h] * 16;
        gB[h] = B + (size_t)(n0 + lrow[h]) * Kx + lchunk[h] * 16;
    }

    const int T = Kx >> 6;   // K / 64

    auto load_stage = [&](int t) {
        uint32_t st = sbase + (uint32_t)(t % STAGES) * STAGE_BYTES;
        size_t kb = (size_t)t * 64;
#pragma unroll
        for (int h = 0; h < 2; h++) cp16(st + soffA[h], gA[h] + kb);
#pragma unroll
        for (int h = 0; h < 2; h++) cp16(st + soffB[h], gB[h] + kb);
        cp_commit();
    };

    int acc[2][8][4];
#pragma unroll
    for (int mt = 0; mt < 2; mt++)
#pragma unroll
        for (int nt = 0; nt < 8; nt++)
#pragma unroll
            for (int r = 0; r < 4; r++) acc[mt][nt][r] = 0;

    // prologue: stages 0..STAGES-2
#pragma unroll
    for (int t = 0; t < STAGES - 1; t++) load_stage(t);

    for (int t = 0; t < T; t++) {
        cp_wait<STAGES - 2>();
        __syncthreads();
        if (t + STAGES - 1 < T) load_stage(t + STAGES - 1);

        const uint32_t st = sbase + (uint32_t)(t % STAGES) * STAGE_BYTES;
#pragma unroll
        for (int ks = 0; ks < 2; ks++) {
            uint32_t a[2][4], b[4][4];
#pragma unroll
            for (int mt = 0; mt < 2; mt++) LDSM4(a[mt], st + offA[mt][ks]);
#pragma unroll
            for (int g = 0; g < 4; g++) LDSM4(b[g], st + offB[g][ks]);
#pragma unroll
            for (int mt = 0; mt < 2; mt++)
#pragma unroll
                for (int nt = 0; nt < 8; nt++) {
                    const int g = nt >> 1, s = (nt & 1) * 2;
                    MMA_S8(acc[mt][nt], a[mt], b[g][s], b[g][s + 1]);
                }
        }
    }

    // ---- epilogue ----
#pragma unroll
    for (int mt = 0; mt < 2; mt++) {
        const int mrow = m0 + warp_m * 32 + mt * 16 + (lane >> 2);
        const float fac0 = wmean / rowScale[mrow];
        const float fac8 = wmean / rowScale[mrow + 8];
        const int colb = n0 + warp_n * 64 + (lane & 3) * 2;
#pragma unroll
        for (int nt = 0; nt < 8; nt++) {
            const int col = colb + nt * 8;
            float v0 = (float)acc[mt][nt][0] * fac0;
            float v1 = (float)acc[mt][nt][1] * fac0;
            float v2 = (float)acc[mt][nt][2] * fac8;
            float v3 = (float)acc[mt][nt][3] * fac8;
            if (mode == 0) {
                v0 = fmaxf(v0, 0.f); v0 *= v0;
                v1 = fmaxf(v1, 0.f); v1 *= v1;
                v2 = fmaxf(v2, 0.f); v2 *= v2;
                v3 = fmaxf(v3, 0.f); v3 *= v3;
            }
            *(float2*)(outp + (size_t)mrow * Nx + col)       = make_float2(v0, v1);
            *(float2*)(outp + (size_t)(mrow + 8) * Nx + col) = make_float2(v2, v3);
        }
    }
}

// ============================ launch ============================
extern "C" void kernel_launch(void* const* d_in, const int* in_sizes, int n_in,
                              void* d_out, int out_size) {
    const float* x  = (const float*)d_in[0];
    const float* w1 = (const float*)d_in[1];
    const float* w2 = (const float*)d_in[2];
    float* out = (float*)d_out;

    cudaFuncSetAttribute(gemm_imma, cudaFuncAttributeMaxDynamicSharedMemorySize, GEMM_SMEM);

    absmean_partial<<<4096, 256>>>(w1);
    absmean_final<<<1, 1024>>>(0);
    absmean_partial<<<4096, 256>>>(w2);
    absmean_final<<<1, 1024>>>(1);

    quantize_w<<<4096, 256>>>(w1, 0);
    quantize_w<<<4096, 256>>>(w2, 1);

    quantize_rows<<<TOKS, 256>>>(x, DDIM, 0);

    gemm_imma<<<dim3(HDIM / 128, TOKS / 128), 256, GEMM_SMEM>>>(0, nullptr);

    quantize_rows<<<TOKS, 256>>>(nullptr, HDIM, 1);

    gemm_imma<<<dim3(DDIM / 128, TOKS / 128), 256, GEMM_SMEM>>>(1, out);
}